// round 5
// baseline (speedup 1.0000x reference)
#include <cuda_runtime.h>
#include <math.h>

#define BATCH   8192
#define NNODES  32
#define DIM     128
#define KDIM    384    // 3*128
#define NPAD    132

// ---- scratch (no allocation allowed) ----
__device__ float g_G[BATCH * KDIM];       // (B, 3*128) weighted feature sums
__device__ float g_wab[12 * DIM];         // rows 0..8: wtop[i*3+j], rows 9..11: wbot[j]
__device__ float g_wb01[2 * DIM];         // interleaved (wbot0[d], wbot1[d]) pairs
__device__ int   g_mask_mode;             // 0=bool/u8, 1=int32, 2=float32

__device__ __forceinline__ float2 ffma2(float2 a, float2 b, float2 c) {
    float2 d;
    asm("{\n\t"
        ".reg .b64 ra, rb, rc, rd;\n\t"
        "mov.b64 ra, {%2,%3};\n\t"
        "mov.b64 rb, {%4,%5};\n\t"
        "mov.b64 rc, {%6,%7};\n\t"
        "fma.rn.f32x2 rd, ra, rb, rc;\n\t"
        "mov.b64 {%0,%1}, rd;\n\t"
        "}"
        : "=f"(d.x), "=f"(d.y)
        : "f"(a.x), "f"(a.y), "f"(b.x), "f"(b.y), "f"(c.x), "f"(c.y));
    return d;
}

// ============================================================
// Kernel 0: blocks 0..11 = weight prep, block 12 = mask sniff
// ============================================================
__global__ __launch_bounds__(256) void prep_detect_kernel(const unsigned int* __restrict__ m,
                                                          const float* __restrict__ W,
                                                          const float* __restrict__ a) {
    if (blockIdx.x == 12) {
        __shared__ int sF, sG;
        if (threadIdx.x == 0) { sF = 0; sG = 0; }
        __syncthreads();
        int f = 0, g = 0;
        for (int i = threadIdx.x; i < 4096; i += blockDim.x) {
            unsigned v = m[i];
            if (v == 0x3F800000u) f = 1;
            else if (v > 1u)      g = 1;
        }
        if (f) atomicOr(&sF, 1);
        if (g) atomicOr(&sG, 1);
        __syncthreads();
        if (threadIdx.x == 0) g_mask_mode = sF ? 2 : (sG ? 0 : 1);
        return;
    }

    const int i    = blockIdx.x >> 2;
    const int quar = blockIdx.x & 3;
    const int wid  = threadIdx.x >> 5;
    const int lane = threadIdx.x & 31;

    const float4 at0 = *(const float4*)&a[0 * 256 + lane * 4];
    const float4 at1 = *(const float4*)&a[1 * 256 + lane * 4];
    const float4 at2 = *(const float4*)&a[2 * 256 + lane * 4];
    const float4 ab  = *(const float4*)&a[i * 256 + 128 + lane * 4];

    #pragma unroll
    for (int r = 0; r < 4; r++) {
        int d = quar * 32 + r * 8 + wid;
        float4 wv = *(const float4*)&W[(size_t)i * (DIM * DIM) + (size_t)d * DIM + lane * 4];
        float s0 = wv.x * at0.x + wv.y * at0.y + wv.z * at0.z + wv.w * at0.w;
        float s1 = wv.x * at1.x + wv.y * at1.y + wv.z * at1.z + wv.w * at1.w;
        float s2 = wv.x * at2.x + wv.y * at2.y + wv.z * at2.z + wv.w * at2.w;
        float sb = wv.x * ab.x  + wv.y * ab.y  + wv.z * ab.z  + wv.w * ab.w;
        #pragma unroll
        for (int off = 16; off > 0; off >>= 1) {
            s0 += __shfl_xor_sync(0xFFFFFFFFu, s0, off);
            s1 += __shfl_xor_sync(0xFFFFFFFFu, s1, off);
            s2 += __shfl_xor_sync(0xFFFFFFFFu, s2, off);
            sb += __shfl_xor_sync(0xFFFFFFFFu, sb, off);
        }
        if (lane == 0) {
            g_wab[(i * 3 + 0) * DIM + d] = s0;
            g_wab[(i * 3 + 1) * DIM + d] = s1;
            g_wab[(i * 3 + 2) * DIM + d] = s2;
            g_wab[(9 + i) * DIM + d]     = sb;
            if (i == 0)      g_wb01[2 * d]     = sb;
            else if (i == 1) g_wb01[2 * d + 1] = sb;
        }
    }
}

// ============================================================
// Kernel 1: attention -> G.  2 batches per 256-thread block.
//   w2[j,n] = p_jn * E_j / Z ; p_jn = exp(sb_jn - lm);
//   E_j = sum_i exp(ls_ij - ml); Z = sum_j E_j * S_j.
// ============================================================
__global__ __launch_bounds__(256) void attn_kernel(const float* __restrict__ hptr,
                                                   const void*  __restrict__ maskp) {
    __shared__ float h_sh[2][NNODES][NPAD];
    __shared__ float sb8_sh[2][3][32][8];   // 8-lane partial sums per (j,node)
    __shared__ float E_sh[2][3];
    __shared__ float S_sh[2][2][3];
    __shared__ float mk_sh[2][3][32];
    __shared__ float w2_sh[2][3][32];

    const int tid  = threadIdx.x;
    const int grp  = tid >> 7;
    const int t    = tid & 127;
    const int w    = t >> 5;
    const int lane = t & 31;
    const int b    = blockIdx.x * 2 + grp;

    // packed bot weights: pairs (wb0,wb1) for this lane's 4 features + wb2
    const float4 wpA = *(const float4*)&g_wb01[lane * 8];       // f0,f1
    const float4 wpB = *(const float4*)&g_wb01[lane * 8 + 4];   // f2,f3
    const float4 wb2 = *(const float4*)&g_wab[11 * DIM + lane * 4];

    // prefetch all 8 h chunks (MLP=8)
    const float4* hp = (const float4*)(hptr + (size_t)b * (NNODES * DIM));
    float4 xs[8];
    #pragma unroll
    for (int v = 0; v < 8; v++) xs[v] = hp[v * 128 + t];

    // mask (3 x 32), normalized to {0,1}
    if (t < 96) {
        int j = t >> 5, node = t & 31;
        size_t idx = (size_t)j * (BATCH * NNODES) + (size_t)b * NNODES + node;
        int mode = g_mask_mode;
        float mv;
        if (mode == 0)      mv = ((const unsigned char*)maskp)[idx] ? 1.f : 0.f;
        else if (mode == 1) mv = ((const int*)maskp)[idx] ? 1.f : 0.f;
        else                mv = (((const float*)maskp)[idx] != 0.f) ? 1.f : 0.f;
        mk_sh[grp][j][node] = mv;
    }

    // ---- store h + partial neighbor logits (reduce to 8-lane classes) ----
    #pragma unroll
    for (int v = 0; v < 8; v++) {
        float4 x = xs[v];
        int node = v * 4 + w;
        *(float4*)&h_sh[grp][node][lane * 4] = x;

        float2 d01 = make_float2(0.f, 0.f);
        d01 = ffma2(make_float2(x.x, x.x), make_float2(wpA.x, wpA.y), d01);
        d01 = ffma2(make_float2(x.y, x.y), make_float2(wpA.z, wpA.w), d01);
        d01 = ffma2(make_float2(x.z, x.z), make_float2(wpB.x, wpB.y), d01);
        d01 = ffma2(make_float2(x.w, x.w), make_float2(wpB.z, wpB.w), d01);
        float d2 = x.x * wb2.x + x.y * wb2.y + x.z * wb2.z + x.w * wb2.w;
        #pragma unroll
        for (int off = 16; off >= 8; off >>= 1) {
            d01.x += __shfl_xor_sync(0xFFFFFFFFu, d01.x, off);
            d01.y += __shfl_xor_sync(0xFFFFFFFFu, d01.y, off);
            d2    += __shfl_xor_sync(0xFFFFFFFFu, d2,    off);
        }
        if (lane < 8 && node > 0) {
            sb8_sh[grp][0][node][lane] = d01.x;
            sb8_sh[grp][1][node][lane] = d01.y;
            sb8_sh[grp][2][node][lane] = d2;
        }
    }
    __syncthreads();

    // ---- phase B ----
    int   jj[2], nd[2];
    bool  act[2];
    float pv[2];

    if (w < 2) {
        const int NN   = (w == 0) ? 15 : 16;
        const int base = (w == 0) ? 1  : 16;
        const int NP   = 3 * NN;

        float sbv[2];
        float lm = -INFINITY;
        #pragma unroll
        for (int r = 0; r < 2; r++) {
            int p = lane + r * 32;
            bool valid = (p < NP);
            int j = valid ? (p / NN) : 0;
            int node = valid ? (base + p % NN) : base;
            jj[r] = j; nd[r] = node;
            float4 sA = *(const float4*)&sb8_sh[grp][j][node][0];
            float4 sB = *(const float4*)&sb8_sh[grp][j][node][4];
            sbv[r] = ((sA.x + sA.y) + (sA.z + sA.w)) + ((sB.x + sB.y) + (sB.z + sB.w));
            bool excl = (mk_sh[grp][j][node] > 0.5f);
            act[r] = valid && !excl;
            if (act[r]) lm = fmaxf(lm, sbv[r]);
        }
        #pragma unroll
        for (int off = 16; off > 0; off >>= 1)
            lm = fmaxf(lm, __shfl_xor_sync(0xFFFFFFFFu, lm, off));

        float b0 = 0.f, b1 = 0.f, b2 = 0.f;
        #pragma unroll
        for (int r = 0; r < 2; r++) {
            pv[r] = 0.f;
            if (act[r]) {
                pv[r] = expf(sbv[r] - lm);
                if (jj[r] == 0) b0 += pv[r];
                else if (jj[r] == 1) b1 += pv[r];
                else b2 += pv[r];
            }
        }
        #pragma unroll
        for (int off = 16; off > 0; off >>= 1) {
            b0 += __shfl_xor_sync(0xFFFFFFFFu, b0, off);
            b1 += __shfl_xor_sync(0xFFFFFFFFu, b1, off);
            b2 += __shfl_xor_sync(0xFFFFFFFFu, b2, off);
        }
        if (lane == 0) {
            S_sh[grp][w][0] = b0;
            S_sh[grp][w][1] = b1;
            S_sh[grp][w][2] = b2;
        }
    } else if (w == 2) {
        // 9 self logits from h_sh[grp][0]
        const float4 x = *(const float4*)&h_sh[grp][0][lane * 4];
        float ls[9];
        #pragma unroll
        for (int q = 0; q < 9; q++) {
            const float4 wt = *(const float4*)&g_wab[q * DIM + lane * 4];
            float dq = x.x * wt.x + x.y * wt.y + x.z * wt.z + x.w * wt.w;
            #pragma unroll
            for (int off = 16; off > 0; off >>= 1)
                dq += __shfl_xor_sync(0xFFFFFFFFu, dq, off);
            ls[q] = dq;
        }
        float ml = ls[0];
        #pragma unroll
        for (int q = 1; q < 9; q++) ml = fmaxf(ml, ls[q]);
        if (lane < 3) {
            float e = expf(ls[0 * 3 + lane] - ml) + expf(ls[1 * 3 + lane] - ml)
                    + expf(ls[2 * 3 + lane] - ml);
            E_sh[grp][lane] = e;
        }
    } else if (w == 3 && lane < 3) {
        w2_sh[grp][lane][0] = mk_sh[grp][lane][0];   // self weights
    }
    __syncthreads();

    // ---- phase C: finalize w2 for neighbor entries ----
    if (w < 2) {
        float E0 = E_sh[grp][0], E1 = E_sh[grp][1], E2 = E_sh[grp][2];
        float S0 = S_sh[grp][w][0], S1 = S_sh[grp][w][1], S2 = S_sh[grp][w][2];
        float Z = E0 * S0 + E1 * S1 + E2 * S2;
        float inv = (Z > 0.f) ? (1.f / Z) : 0.f;
        float Ej[3] = {E0 * inv, E1 * inv, E2 * inv};
        #pragma unroll
        for (int r = 0; r < 2; r++) {
            int p = lane + r * 32;
            const int NP = (w == 0) ? 45 : 48;
            if (p < NP) w2_sh[grp][jj[r]][nd[r]] = pv[r] * Ej[jj[r]];
        }
    }
    __syncthreads();

    // ---- G[b, j*128 + t] = sum_n w2[j][n] * h[b, n, t] ----
    float g0 = 0.f, g1 = 0.f, g2 = 0.f;
    #pragma unroll
    for (int n = 0; n < NNODES; n++) {
        float hv = h_sh[grp][n][t];
        g0 += w2_sh[grp][0][n] * hv;
        g1 += w2_sh[grp][1][n] * hv;
        g2 += w2_sh[grp][2][n] * hv;
    }
    float* Gp = g_G + (size_t)b * KDIM;
    Gp[t]       = g0;
    Gp[128 + t] = g1;
    Gp[256 + t] = g2;
}

// ============================================================
// Kernel 2: out = elu( G (8192x384) @ W (384x128) ), fused.
//   32-row x 128-col tiles, grid 256.  W re-reads hit L2.
// ============================================================
__global__ __launch_bounds__(256) void gemm_elu_kernel(const float* __restrict__ W,
                                                       float* __restrict__ out) {
    __shared__ float Gs[32][33];     // pad 33: conflict-free scalar stores
    __shared__ float Ws[32][132];

    const int tid  = threadIdx.x;
    const int w    = tid >> 5;       // warp -> rows w*4..w*4+3
    const int lane = tid & 31;       // lane -> cols lane*4..+3
    const int row0 = blockIdx.x * 32;

    float2 acc[4][2];
    #pragma unroll
    for (int i = 0; i < 4; i++) { acc[i][0] = make_float2(0.f, 0.f); acc[i][1] = make_float2(0.f, 0.f); }

    for (int k0 = 0; k0 < KDIM; k0 += 32) {
        {   // G tile 32x32
            int r = tid >> 3, c = (tid & 7) * 4;
            float4 x = *(const float4*)(g_G + (size_t)(row0 + r) * KDIM + k0 + c);
            Gs[r][c + 0] = x.x; Gs[r][c + 1] = x.y; Gs[r][c + 2] = x.z; Gs[r][c + 3] = x.w;
        }
        #pragma unroll
        for (int v = 0; v < 4; v++) {   // W tile 32x128 (W is contiguous 384x128)
            int f = tid + v * 256;
            int r = f >> 5, c = (f & 31) * 4;
            *(float4*)&Ws[r][c] = *(const float4*)(W + (size_t)(k0 + r) * DIM + c);
        }
        __syncthreads();

        #pragma unroll
        for (int kk = 0; kk < 32; kk++) {
            float4 bv = *(const float4*)&Ws[kk][lane * 4];
            float2 b01 = make_float2(bv.x, bv.y);
            float2 b23 = make_float2(bv.z, bv.w);
            #pragma unroll
            for (int i = 0; i < 4; i++) {
                float a = Gs[w * 4 + i][kk];              // broadcast
                float2 a2 = make_float2(a, a);
                acc[i][0] = ffma2(a2, b01, acc[i][0]);
                acc[i][1] = ffma2(a2, b23, acc[i][1]);
            }
        }
        __syncthreads();
    }

    #pragma unroll
    for (int i = 0; i < 4; i++) {
        int r = row0 + w * 4 + i;
        float4 v;
        v.x = acc[i][0].x; v.y = acc[i][0].y; v.z = acc[i][1].x; v.w = acc[i][1].y;
        v.x = (v.x > 0.f) ? v.x : expm1f(v.x);
        v.y = (v.y > 0.f) ? v.y : expm1f(v.y);
        v.z = (v.z > 0.f) ? v.z : expm1f(v.z);
        v.w = (v.w > 0.f) ? v.w : expm1f(v.w);
        *(float4*)(out + (size_t)r * DIM + lane * 4) = v;
    }
}

// ============================================================
extern "C" void kernel_launch(void* const* d_in, const int* in_sizes, int n_in,
                              void* d_out, int out_size) {
    const float* h    = (const float*)d_in[0];
    const void*  mask = d_in[1];
    const float* W    = (const float*)d_in[5];
    const float* a    = (const float*)d_in[6];
    float* out = (float*)d_out;

    prep_detect_kernel<<<13, 256>>>((const unsigned int*)mask, W, a);
    attn_kernel<<<BATCH / 2, 256>>>(h, mask);
    gemm_elu_kernel<<<BATCH / 32, 256>>>(W, out);
}

// round 6
// speedup vs baseline: 1.0067x; 1.0067x over previous
#include <cuda_runtime.h>
#include <math.h>

#define BATCH   8192
#define NNODES  32
#define DIM     128
#define KDIM    384    // 3*128
#define NPAD    132

// ---- scratch (no allocation allowed) ----
__device__ float g_G[BATCH * KDIM];       // (B, 3*128) weighted feature sums
__device__ float g_wab[12 * DIM];         // rows 0..8: wtop[i*3+j], rows 9..11: wbot[j]
__device__ float g_wb01[2 * DIM];         // interleaved (wbot0[d], wbot1[d]) pairs
__device__ int   g_mask_mode;             // 0=bool/u8, 1=int32, 2=float32

__device__ __forceinline__ float2 ffma2(float2 a, float2 b, float2 c) {
    float2 d;
    asm("{\n\t"
        ".reg .b64 ra, rb, rc, rd;\n\t"
        "mov.b64 ra, {%2,%3};\n\t"
        "mov.b64 rb, {%4,%5};\n\t"
        "mov.b64 rc, {%6,%7};\n\t"
        "fma.rn.f32x2 rd, ra, rb, rc;\n\t"
        "mov.b64 {%0,%1}, rd;\n\t"
        "}"
        : "=f"(d.x), "=f"(d.y)
        : "f"(a.x), "f"(a.y), "f"(b.x), "f"(b.y), "f"(c.x), "f"(c.y));
    return d;
}

// ============================================================
// Kernel 0: blocks 0..11 = weight prep, block 12 = mask sniff
// ============================================================
__global__ __launch_bounds__(256) void prep_detect_kernel(const unsigned int* __restrict__ m,
                                                          const float* __restrict__ W,
                                                          const float* __restrict__ a) {
    if (blockIdx.x == 12) {
        __shared__ int sF, sG;
        if (threadIdx.x == 0) { sF = 0; sG = 0; }
        __syncthreads();
        int f = 0, g = 0;
        #pragma unroll
        for (int r = 0; r < 8; r++) {
            unsigned v = m[r * 256 + threadIdx.x];
            if (v == 0x3F800000u) f = 1;
            else if (v > 1u)      g = 1;
        }
        if (f) atomicOr(&sF, 1);
        if (g) atomicOr(&sG, 1);
        __syncthreads();
        if (threadIdx.x == 0) g_mask_mode = sF ? 2 : (sG ? 0 : 1);
        return;
    }

    const int i    = blockIdx.x >> 2;
    const int quar = blockIdx.x & 3;
    const int wid  = threadIdx.x >> 5;
    const int lane = threadIdx.x & 31;

    const float4 at0 = *(const float4*)&a[0 * 256 + lane * 4];
    const float4 at1 = *(const float4*)&a[1 * 256 + lane * 4];
    const float4 at2 = *(const float4*)&a[2 * 256 + lane * 4];
    const float4 ab  = *(const float4*)&a[i * 256 + 128 + lane * 4];

    #pragma unroll
    for (int r = 0; r < 4; r++) {
        int d = quar * 32 + r * 8 + wid;
        float4 wv = *(const float4*)&W[(size_t)i * (DIM * DIM) + (size_t)d * DIM + lane * 4];
        float s0 = wv.x * at0.x + wv.y * at0.y + wv.z * at0.z + wv.w * at0.w;
        float s1 = wv.x * at1.x + wv.y * at1.y + wv.z * at1.z + wv.w * at1.w;
        float s2 = wv.x * at2.x + wv.y * at2.y + wv.z * at2.z + wv.w * at2.w;
        float sb = wv.x * ab.x  + wv.y * ab.y  + wv.z * ab.z  + wv.w * ab.w;
        #pragma unroll
        for (int off = 16; off > 0; off >>= 1) {
            s0 += __shfl_xor_sync(0xFFFFFFFFu, s0, off);
            s1 += __shfl_xor_sync(0xFFFFFFFFu, s1, off);
            s2 += __shfl_xor_sync(0xFFFFFFFFu, s2, off);
            sb += __shfl_xor_sync(0xFFFFFFFFu, sb, off);
        }
        if (lane == 0) {
            g_wab[(i * 3 + 0) * DIM + d] = s0;
            g_wab[(i * 3 + 1) * DIM + d] = s1;
            g_wab[(i * 3 + 2) * DIM + d] = s2;
            g_wab[(9 + i) * DIM + d]     = sb;
            if (i == 0)      g_wb01[2 * d]     = sb;
            else if (i == 1) g_wb01[2 * d + 1] = sb;
        }
    }
}

// ============================================================
// Kernel 1: attention -> G.  2 batches per 256-thread block.
//   w2[j,n] = p_jn * E_j / Z ; p_jn = exp(sb_jn - lm);
//   E_j = sum_i exp(ls_ij - ml); Z = sum_j E_j * S_j.
//   Final weights stored n-major (w2n[n][j]) -> one LDS.128 per n.
// ============================================================
__global__ __launch_bounds__(256) void attn_kernel(const float* __restrict__ hptr,
                                                   const void*  __restrict__ maskp) {
    __shared__ float h_sh[2][NNODES][NPAD];
    __shared__ float sb8_sh[2][3][32][8];   // 8-lane partial sums per (j,node)
    __shared__ float E_sh[2][3];
    __shared__ float mk_sh[2][3][32];
    __shared__ float4 w2n_sh[2][32];        // (w2_0, w2_1, w2_2, pad) per node

    const int tid  = threadIdx.x;
    const int grp  = tid >> 7;
    const int t    = tid & 127;
    const int w    = t >> 5;
    const int lane = t & 31;
    const int b    = blockIdx.x * 2 + grp;

    // packed bot weights: pairs (wb0,wb1) for this lane's 4 features + wb2
    const float4 wpA = *(const float4*)&g_wb01[lane * 8];       // f0,f1
    const float4 wpB = *(const float4*)&g_wb01[lane * 8 + 4];   // f2,f3
    const float4 wb2 = *(const float4*)&g_wab[11 * DIM + lane * 4];

    // prefetch all 8 h chunks (MLP=8)
    const float4* hp = (const float4*)(hptr + (size_t)b * (NNODES * DIM));
    float4 xs[8];
    #pragma unroll
    for (int v = 0; v < 8; v++) xs[v] = hp[v * 128 + t];

    // mask (3 x 32), normalized to {0,1}
    if (t < 96) {
        int j = t >> 5, node = t & 31;
        size_t idx = (size_t)j * (BATCH * NNODES) + (size_t)b * NNODES + node;
        int mode = g_mask_mode;
        float mv;
        if (mode == 0)      mv = ((const unsigned char*)maskp)[idx] ? 1.f : 0.f;
        else if (mode == 1) mv = ((const int*)maskp)[idx] ? 1.f : 0.f;
        else                mv = (((const float*)maskp)[idx] != 0.f) ? 1.f : 0.f;
        mk_sh[grp][j][node] = mv;
    }

    // ---- store h + partial neighbor logits (reduce to 8-lane classes) ----
    #pragma unroll
    for (int v = 0; v < 8; v++) {
        float4 x = xs[v];
        int node = v * 4 + w;
        *(float4*)&h_sh[grp][node][lane * 4] = x;

        float2 d01 = make_float2(0.f, 0.f);
        d01 = ffma2(make_float2(x.x, x.x), make_float2(wpA.x, wpA.y), d01);
        d01 = ffma2(make_float2(x.y, x.y), make_float2(wpA.z, wpA.w), d01);
        d01 = ffma2(make_float2(x.z, x.z), make_float2(wpB.x, wpB.y), d01);
        d01 = ffma2(make_float2(x.w, x.w), make_float2(wpB.z, wpB.w), d01);
        float d2 = x.x * wb2.x + x.y * wb2.y + x.z * wb2.z + x.w * wb2.w;
        #pragma unroll
        for (int off = 16; off >= 8; off >>= 1) {
            d01.x += __shfl_xor_sync(0xFFFFFFFFu, d01.x, off);
            d01.y += __shfl_xor_sync(0xFFFFFFFFu, d01.y, off);
            d2    += __shfl_xor_sync(0xFFFFFFFFu, d2,    off);
        }
        if (lane < 8 && node > 0) {
            sb8_sh[grp][0][node][lane] = d01.x;
            sb8_sh[grp][1][node][lane] = d01.y;
            sb8_sh[grp][2][node][lane] = d2;
        }
    }
    __syncthreads();

    // ---- phase B ----
    int   jj[2], nd[2];
    bool  act[2];
    float pv[2];
    float Sreg[3] = {0.f, 0.f, 0.f};

    if (w < 2) {
        const int NN   = (w == 0) ? 15 : 16;
        const int base = (w == 0) ? 1  : 16;
        const int NP   = 3 * NN;

        float sbv[2];
        float lm = -INFINITY;
        #pragma unroll
        for (int r = 0; r < 2; r++) {
            int p = lane + r * 32;
            bool valid = (p < NP);
            int j = valid ? (p / NN) : 0;
            int node = valid ? (base + p % NN) : base;
            jj[r] = j; nd[r] = node;
            float4 sA = *(const float4*)&sb8_sh[grp][j][node][0];
            float4 sB = *(const float4*)&sb8_sh[grp][j][node][4];
            sbv[r] = ((sA.x + sA.y) + (sA.z + sA.w)) + ((sB.x + sB.y) + (sB.z + sB.w));
            bool excl = (mk_sh[grp][j][node] > 0.5f);
            act[r] = valid && !excl;
            if (act[r]) lm = fmaxf(lm, sbv[r]);
        }
        #pragma unroll
        for (int off = 16; off > 0; off >>= 1)
            lm = fmaxf(lm, __shfl_xor_sync(0xFFFFFFFFu, lm, off));

        #pragma unroll
        for (int r = 0; r < 2; r++) {
            pv[r] = 0.f;
            if (act[r]) {
                pv[r] = expf(sbv[r] - lm);
                Sreg[jj[r]] += pv[r];
            }
        }
        #pragma unroll
        for (int off = 16; off > 0; off >>= 1) {
            Sreg[0] += __shfl_xor_sync(0xFFFFFFFFu, Sreg[0], off);
            Sreg[1] += __shfl_xor_sync(0xFFFFFFFFu, Sreg[1], off);
            Sreg[2] += __shfl_xor_sync(0xFFFFFFFFu, Sreg[2], off);
        }
    } else if (w == 2) {
        // 9 self logits from h_sh[grp][0]
        const float4 x = *(const float4*)&h_sh[grp][0][lane * 4];
        float ls[9];
        #pragma unroll
        for (int q = 0; q < 9; q++) {
            const float4 wt = *(const float4*)&g_wab[q * DIM + lane * 4];
            float dq = x.x * wt.x + x.y * wt.y + x.z * wt.z + x.w * wt.w;
            #pragma unroll
            for (int off = 16; off > 0; off >>= 1)
                dq += __shfl_xor_sync(0xFFFFFFFFu, dq, off);
            ls[q] = dq;
        }
        float ml = ls[0];
        #pragma unroll
        for (int q = 1; q < 9; q++) ml = fmaxf(ml, ls[q]);
        if (lane < 3) {
            float e = expf(ls[0 * 3 + lane] - ml) + expf(ls[1 * 3 + lane] - ml)
                    + expf(ls[2 * 3 + lane] - ml);
            E_sh[grp][lane] = e;
        }
    } else if (w == 3 && lane < 3) {
        // self weights into node-0 slot (scalar writes to x/y/z components)
        ((float*)&w2n_sh[grp][0])[lane] = mk_sh[grp][lane][0];
    }
    __syncthreads();

    // ---- phase C: finalize w2 (n-major layout) ----
    if (w < 2) {
        float E0 = E_sh[grp][0], E1 = E_sh[grp][1], E2 = E_sh[grp][2];
        float Z = E0 * Sreg[0] + E1 * Sreg[1] + E2 * Sreg[2];
        float inv = (Z > 0.f) ? (1.f / Z) : 0.f;
        float Ej[3] = {E0 * inv, E1 * inv, E2 * inv};
        #pragma unroll
        for (int r = 0; r < 2; r++) {
            int p = lane + r * 32;
            const int NP = (w == 0) ? 45 : 48;
            if (p < NP) ((float*)&w2n_sh[grp][nd[r]])[jj[r]] = pv[r] * Ej[jj[r]];
        }
    }
    __syncthreads();

    // ---- G[b, j*128 + t] = sum_n w2[j][n] * h[b, n, t] ----
    float g0 = 0.f, g1 = 0.f, g2 = 0.f;
    #pragma unroll
    for (int n = 0; n < NNODES; n++) {
        float4 wv = w2n_sh[grp][n];          // LDS.128 broadcast
        float hv = h_sh[grp][n][t];
        g0 += wv.x * hv;
        g1 += wv.y * hv;
        g2 += wv.z * hv;
    }
    float* Gp = g_G + (size_t)b * KDIM;
    Gp[t]       = g0;
    Gp[128 + t] = g1;
    Gp[256 + t] = g2;
}

// ============================================================
// Kernel 2: out = elu( G (8192x384) @ W (384x128) ), fused.
//   32-row x 128-col tiles, grid 256.  Register-prefetch pipeline.
// ============================================================
__global__ __launch_bounds__(256) void gemm_elu_kernel(const float* __restrict__ W,
                                                       float* __restrict__ out) {
    __shared__ float Gs[32][33];     // pad 33: conflict-free scalar stores
    __shared__ float Ws[32][132];

    const int tid  = threadIdx.x;
    const int w    = tid >> 5;       // warp -> rows w*4..w*4+3
    const int lane = tid & 31;       // lane -> cols lane*4..+3
    const int row0 = blockIdx.x * 32;

    // per-thread load coordinates
    const int gr = tid >> 3, gc = (tid & 7) * 4;           // G tile slot
    const float* gsrc = g_G + (size_t)(row0 + gr) * KDIM + gc;

    float2 acc[4][2];
    #pragma unroll
    for (int i = 0; i < 4; i++) { acc[i][0] = make_float2(0.f, 0.f); acc[i][1] = make_float2(0.f, 0.f); }

    // prefetch tile 0
    float4 gx = *(const float4*)gsrc;
    float4 wx[4];
    #pragma unroll
    for (int v = 0; v < 4; v++) {
        int f = tid + v * 256;
        wx[v] = *(const float4*)(W + (size_t)(f >> 5) * DIM + (f & 31) * 4);
    }

    #pragma unroll 1
    for (int k0 = 0; k0 < KDIM; k0 += 32) {
        // store current tile
        Gs[gr][gc + 0] = gx.x; Gs[gr][gc + 1] = gx.y;
        Gs[gr][gc + 2] = gx.z; Gs[gr][gc + 3] = gx.w;
        #pragma unroll
        for (int v = 0; v < 4; v++) {
            int f = tid + v * 256;
            *(float4*)&Ws[f >> 5][(f & 31) * 4] = wx[v];
        }
        __syncthreads();

        // prefetch next tile while computing
        if (k0 + 32 < KDIM) {
            gx = *(const float4*)(gsrc + k0 + 32);
            #pragma unroll
            for (int v = 0; v < 4; v++) {
                int f = tid + v * 256;
                wx[v] = *(const float4*)(W + (size_t)(k0 + 32 + (f >> 5)) * DIM + (f & 31) * 4);
            }
        }

        #pragma unroll
        for (int kk = 0; kk < 32; kk++) {
            float4 bv = *(const float4*)&Ws[kk][lane * 4];
            float2 b01 = make_float2(bv.x, bv.y);
            float2 b23 = make_float2(bv.z, bv.w);
            #pragma unroll
            for (int i = 0; i < 4; i++) {
                float a = Gs[w * 4 + i][kk];              // broadcast
                float2 a2 = make_float2(a, a);
                acc[i][0] = ffma2(a2, b01, acc[i][0]);
                acc[i][1] = ffma2(a2, b23, acc[i][1]);
            }
        }
        __syncthreads();
    }

    #pragma unroll
    for (int i = 0; i < 4; i++) {
        int r = row0 + w * 4 + i;
        float4 v;
        v.x = acc[i][0].x; v.y = acc[i][0].y; v.z = acc[i][1].x; v.w = acc[i][1].y;
        v.x = (v.x > 0.f) ? v.x : expm1f(v.x);
        v.y = (v.y > 0.f) ? v.y : expm1f(v.y);
        v.z = (v.z > 0.f) ? v.z : expm1f(v.z);
        v.w = (v.w > 0.f) ? v.w : expm1f(v.w);
        *(float4*)(out + (size_t)r * DIM + lane * 4) = v;
    }
}

// ============================================================
extern "C" void kernel_launch(void* const* d_in, const int* in_sizes, int n_in,
                              void* d_out, int out_size) {
    const float* h    = (const float*)d_in[0];
    const void*  mask = d_in[1];
    const float* W    = (const float*)d_in[5];
    const float* a    = (const float*)d_in[6];
    float* out = (float*)d_out;

    prep_detect_kernel<<<13, 256>>>((const unsigned int*)mask, W, a);
    attn_kernel<<<BATCH / 2, 256>>>(h, mask);
    gemm_elu_kernel<<<BATCH / 32, 256>>>(W, out);
}

// round 7
// speedup vs baseline: 1.1069x; 1.0995x over previous
#include <cuda_runtime.h>
#include <math.h>

#define BATCH   8192
#define NNODES  32
#define DIM     128
#define KDIM    384    // 3*128

// ---- scratch (no allocation allowed) ----
__device__ float g_G[BATCH * KDIM];       // (B, 3*128) weighted feature sums
__device__ float g_P[3 * BATCH * DIM];    // split-K partials
__device__ float g_wab[12 * DIM];         // rows 0..8: wtop[i*3+j], rows 9..11: wbot[j]
__device__ float g_wb01[2 * DIM];         // interleaved (wbot0[d], wbot1[d]) pairs
__device__ int   g_mask_mode;             // 0=bool/u8, 1=int32, 2=float32

__device__ __forceinline__ float2 ffma2(float2 a, float2 b, float2 c) {
    float2 d;
    asm("{\n\t"
        ".reg .b64 ra, rb, rc, rd;\n\t"
        "mov.b64 ra, {%2,%3};\n\t"
        "mov.b64 rb, {%4,%5};\n\t"
        "mov.b64 rc, {%6,%7};\n\t"
        "fma.rn.f32x2 rd, ra, rb, rc;\n\t"
        "mov.b64 {%0,%1}, rd;\n\t"
        "}"
        : "=f"(d.x), "=f"(d.y)
        : "f"(a.x), "f"(a.y), "f"(b.x), "f"(b.y), "f"(c.x), "f"(c.y));
    return d;
}

// ============================================================
// Kernel 0: blocks 0..11 = weight prep, block 12 = mask sniff
// ============================================================
__global__ __launch_bounds__(256) void prep_detect_kernel(const unsigned int* __restrict__ m,
                                                          const float* __restrict__ W,
                                                          const float* __restrict__ a) {
    if (blockIdx.x == 12) {
        __shared__ int sF, sG;
        if (threadIdx.x == 0) { sF = 0; sG = 0; }
        __syncthreads();
        int f = 0, g = 0;
        #pragma unroll
        for (int r = 0; r < 8; r++) {
            unsigned v = m[r * 256 + threadIdx.x];
            if (v == 0x3F800000u) f = 1;
            else if (v > 1u)      g = 1;
        }
        if (f) atomicOr(&sF, 1);
        if (g) atomicOr(&sG, 1);
        __syncthreads();
        if (threadIdx.x == 0) g_mask_mode = sF ? 2 : (sG ? 0 : 1);
        return;
    }

    const int i    = blockIdx.x >> 2;
    const int quar = blockIdx.x & 3;
    const int wid  = threadIdx.x >> 5;
    const int lane = threadIdx.x & 31;

    const float4 at0 = *(const float4*)&a[0 * 256 + lane * 4];
    const float4 at1 = *(const float4*)&a[1 * 256 + lane * 4];
    const float4 at2 = *(const float4*)&a[2 * 256 + lane * 4];
    const float4 ab  = *(const float4*)&a[i * 256 + 128 + lane * 4];

    // prefetch all 4 W rows (MLP=4)
    float4 wv[4];
    #pragma unroll
    for (int r = 0; r < 4; r++) {
        int d = quar * 32 + r * 8 + wid;
        wv[r] = *(const float4*)&W[(size_t)i * (DIM * DIM) + (size_t)d * DIM + lane * 4];
    }

    #pragma unroll
    for (int r = 0; r < 4; r++) {
        int d = quar * 32 + r * 8 + wid;
        float4 x = wv[r];
        float s0 = x.x * at0.x + x.y * at0.y + x.z * at0.z + x.w * at0.w;
        float s1 = x.x * at1.x + x.y * at1.y + x.z * at1.z + x.w * at1.w;
        float s2 = x.x * at2.x + x.y * at2.y + x.z * at2.z + x.w * at2.w;
        float sb = x.x * ab.x  + x.y * ab.y  + x.z * ab.z  + x.w * ab.w;
        #pragma unroll
        for (int off = 16; off > 0; off >>= 1) {
            s0 += __shfl_xor_sync(0xFFFFFFFFu, s0, off);
            s1 += __shfl_xor_sync(0xFFFFFFFFu, s1, off);
            s2 += __shfl_xor_sync(0xFFFFFFFFu, s2, off);
            sb += __shfl_xor_sync(0xFFFFFFFFu, sb, off);
        }
        if (lane == 0) {
            g_wab[(i * 3 + 0) * DIM + d] = s0;
            g_wab[(i * 3 + 1) * DIM + d] = s1;
            g_wab[(i * 3 + 2) * DIM + d] = s2;
            g_wab[(9 + i) * DIM + d]     = sb;
            if (i == 0)      g_wb01[2 * d]     = sb;
            else if (i == 1) g_wb01[2 * d + 1] = sb;
        }
    }
}

// ============================================================
// Kernel 1: attention -> G.  128 threads = 1 batch, grid 8192.
//   h stays in registers (xs[8]); no h smem tile.
//   Final G via per-thread register accumulation + 4-warp
//   partial reduction through a small smem buffer.
// ============================================================
__global__ __launch_bounds__(128, 6) void attn_kernel(const float* __restrict__ hptr,
                                                      const void*  __restrict__ maskp) {
    __shared__ float h0_sh[DIM];            // node-0 features (self logits)
    __shared__ float sb8_sh[3][32][8];      // 8-lane partial sums per (j,node)
    __shared__ float E_sh[3];
    __shared__ float mk_sh[3][32];
    __shared__ float4 w2n_sh[32];           // (w2_0, w2_1, w2_2, pad) per node
    __shared__ float part_sh[4][3][DIM];    // per-warp partial G

    const int t    = threadIdx.x;
    const int w    = t >> 5;
    const int lane = t & 31;
    const int b    = blockIdx.x;

    // packed bot weights: pairs (wb0,wb1) for this lane's 4 features + wb2
    const float4 wpA = *(const float4*)&g_wb01[lane * 8];       // f0,f1
    const float4 wpB = *(const float4*)&g_wb01[lane * 8 + 4];   // f2,f3
    const float4 wb2 = *(const float4*)&g_wab[11 * DIM + lane * 4];

    // prefetch all 8 h chunks (MLP=8); thread owns nodes v*4+w, feats lane*4..+3
    const float4* hp = (const float4*)(hptr + (size_t)b * (NNODES * DIM));
    float4 xs[8];
    #pragma unroll
    for (int v = 0; v < 8; v++) xs[v] = hp[v * 128 + t];

    // mask (3 x 32), normalized to {0,1}
    if (t < 96) {
        int j = t >> 5, node = t & 31;
        size_t idx = (size_t)j * (BATCH * NNODES) + (size_t)b * NNODES + node;
        int mode = g_mask_mode;
        float mv;
        if (mode == 0)      mv = ((const unsigned char*)maskp)[idx] ? 1.f : 0.f;
        else if (mode == 1) mv = ((const int*)maskp)[idx] ? 1.f : 0.f;
        else                mv = (((const float*)maskp)[idx] != 0.f) ? 1.f : 0.f;
        mk_sh[j][node] = mv;
    }

    // ---- neighbor logit partials (reduce to 8-lane classes) ----
    #pragma unroll
    for (int v = 0; v < 8; v++) {
        float4 x = xs[v];
        int node = v * 4 + w;
        if (v == 0 && w == 0)
            *(float4*)&h0_sh[lane * 4] = x;     // stage node 0 for self logits

        float2 d01 = make_float2(0.f, 0.f);
        d01 = ffma2(make_float2(x.x, x.x), make_float2(wpA.x, wpA.y), d01);
        d01 = ffma2(make_float2(x.y, x.y), make_float2(wpA.z, wpA.w), d01);
        d01 = ffma2(make_float2(x.z, x.z), make_float2(wpB.x, wpB.y), d01);
        d01 = ffma2(make_float2(x.w, x.w), make_float2(wpB.z, wpB.w), d01);
        float d2 = x.x * wb2.x + x.y * wb2.y + x.z * wb2.z + x.w * wb2.w;
        #pragma unroll
        for (int off = 16; off >= 8; off >>= 1) {
            d01.x += __shfl_xor_sync(0xFFFFFFFFu, d01.x, off);
            d01.y += __shfl_xor_sync(0xFFFFFFFFu, d01.y, off);
            d2    += __shfl_xor_sync(0xFFFFFFFFu, d2,    off);
        }
        if (lane < 8 && node > 0) {
            sb8_sh[0][node][lane] = d01.x;
            sb8_sh[1][node][lane] = d01.y;
            sb8_sh[2][node][lane] = d2;
        }
    }
    __syncthreads();

    // ---- phase B: warp 0 = ally, warp 1 = opp, warp 2 = self logits ----
    int   jj[2], nd[2];
    bool  act[2];
    float pv[2];
    float Sreg[3] = {0.f, 0.f, 0.f};

    if (w < 2) {
        const int NN   = (w == 0) ? 15 : 16;
        const int base = (w == 0) ? 1  : 16;
        const int NP   = 3 * NN;

        float sbv[2];
        float lm = -INFINITY;
        #pragma unroll
        for (int r = 0; r < 2; r++) {
            int p = lane + r * 32;
            bool valid = (p < NP);
            int j = valid ? (p / NN) : 0;
            int node = valid ? (base + p % NN) : base;
            jj[r] = j; nd[r] = node;
            float4 sA = *(const float4*)&sb8_sh[j][node][0];
            float4 sB = *(const float4*)&sb8_sh[j][node][4];
            sbv[r] = ((sA.x + sA.y) + (sA.z + sA.w)) + ((sB.x + sB.y) + (sB.z + sB.w));
            bool excl = (mk_sh[j][node] > 0.5f);
            act[r] = valid && !excl;
            if (act[r]) lm = fmaxf(lm, sbv[r]);
        }
        #pragma unroll
        for (int off = 16; off > 0; off >>= 1)
            lm = fmaxf(lm, __shfl_xor_sync(0xFFFFFFFFu, lm, off));

        #pragma unroll
        for (int r = 0; r < 2; r++) {
            pv[r] = 0.f;
            if (act[r]) {
                pv[r] = expf(sbv[r] - lm);
                Sreg[jj[r]] += pv[r];
            }
        }
        #pragma unroll
        for (int off = 16; off > 0; off >>= 1) {
            Sreg[0] += __shfl_xor_sync(0xFFFFFFFFu, Sreg[0], off);
            Sreg[1] += __shfl_xor_sync(0xFFFFFFFFu, Sreg[1], off);
            Sreg[2] += __shfl_xor_sync(0xFFFFFFFFu, Sreg[2], off);
        }
    } else if (w == 2) {
        const float4 x = *(const float4*)&h0_sh[lane * 4];
        float ls[9];
        #pragma unroll
        for (int q = 0; q < 9; q++) {
            const float4 wt = *(const float4*)&g_wab[q * DIM + lane * 4];
            float dq = x.x * wt.x + x.y * wt.y + x.z * wt.z + x.w * wt.w;
            #pragma unroll
            for (int off = 16; off > 0; off >>= 1)
                dq += __shfl_xor_sync(0xFFFFFFFFu, dq, off);
            ls[q] = dq;
        }
        float ml = ls[0];
        #pragma unroll
        for (int q = 1; q < 9; q++) ml = fmaxf(ml, ls[q]);
        if (lane < 3) {
            float e = expf(ls[0 * 3 + lane] - ml) + expf(ls[1 * 3 + lane] - ml)
                    + expf(ls[2 * 3 + lane] - ml);
            E_sh[lane] = e;
        }
    } else if (w == 3 && lane < 3) {
        ((float*)&w2n_sh[0])[lane] = mk_sh[lane][0];   // self weights
    }
    __syncthreads();

    // ---- phase C: finalize w2 (n-major float4 per node) ----
    if (w < 2) {
        float E0 = E_sh[0], E1 = E_sh[1], E2 = E_sh[2];
        float Z = E0 * Sreg[0] + E1 * Sreg[1] + E2 * Sreg[2];
        float inv = (Z > 0.f) ? (1.f / Z) : 0.f;
        float Ej[3] = {E0 * inv, E1 * inv, E2 * inv};
        #pragma unroll
        for (int r = 0; r < 2; r++) {
            int p = lane + r * 32;
            const int NP = (w == 0) ? 45 : 48;
            if (p < NP) ((float*)&w2n_sh[nd[r]])[jj[r]] = pv[r] * Ej[jj[r]];
        }
    }
    __syncthreads();

    // ---- register-resident accumulation: thread covers its 8 nodes ----
    float4 a0 = make_float4(0.f, 0.f, 0.f, 0.f);
    float4 a1 = a0, a2 = a0;
    #pragma unroll
    for (int v = 0; v < 8; v++) {
        float4 wv = w2n_sh[v * 4 + w];      // LDS.128 broadcast
        float4 x = xs[v];
        a0.x += wv.x * x.x; a0.y += wv.x * x.y; a0.z += wv.x * x.z; a0.w += wv.x * x.w;
        a1.x += wv.y * x.x; a1.y += wv.y * x.y; a1.z += wv.y * x.z; a1.w += wv.y * x.w;
        a2.x += wv.z * x.x; a2.y += wv.z * x.y; a2.z += wv.z * x.z; a2.w += wv.z * x.w;
    }
    *(float4*)&part_sh[w][0][lane * 4] = a0;
    *(float4*)&part_sh[w][1][lane * 4] = a1;
    *(float4*)&part_sh[w][2][lane * 4] = a2;
    __syncthreads();

    // ---- cross-warp sum: thread t emits G[b, j*128 + t] for j=0..2 ----
    float* Gp = g_G + (size_t)b * KDIM;
    #pragma unroll
    for (int j = 0; j < 3; j++) {
        float s = (part_sh[0][j][t] + part_sh[1][j][t])
                + (part_sh[2][j][t] + part_sh[3][j][t]);
        Gp[j * DIM + t] = s;
    }
}

// ============================================================
// Kernel 2: split-K GEMM.  P[j] = G_j (8192x128) @ W_j (128x128)
//   64 rows x 128 cols, transposed-G broadcast reads.
// ============================================================
__global__ __launch_bounds__(256) void gemm_split_kernel(const float* __restrict__ W) {
    __shared__ float Gst[32][68];    // [kk][row], transposed
    __shared__ float Ws[32][132];    // [kk][col]

    const int tid  = threadIdx.x;
    const int w    = tid >> 5;
    const int lane = tid & 31;
    const int row0 = blockIdx.x * 64;
    const int j    = blockIdx.y;

    float2 acc[8][2];
    #pragma unroll
    for (int i = 0; i < 8; i++) { acc[i][0] = make_float2(0.f, 0.f); acc[i][1] = make_float2(0.f, 0.f); }

    for (int k0 = 0; k0 < 128; k0 += 32) {
        #pragma unroll
        for (int v = 0; v < 2; v++) {                 // G 64x32 -> transposed
            int f = tid + v * 256;
            int r = f >> 3, c = (f & 7) * 4;
            float4 x = *(const float4*)(g_G + (size_t)(row0 + r) * KDIM + j * 128 + k0 + c);
            Gst[c + 0][r] = x.x; Gst[c + 1][r] = x.y; Gst[c + 2][r] = x.z; Gst[c + 3][r] = x.w;
        }
        #pragma unroll
        for (int v = 0; v < 4; v++) {                 // W 32x128
            int f = tid + v * 256;
            int r = f >> 5, c = (f & 31) * 4;
            *(float4*)&Ws[r][c] = *(const float4*)(W + (size_t)j * (DIM * DIM) + (size_t)(k0 + r) * DIM + c);
        }
        __syncthreads();

        #pragma unroll
        for (int kk = 0; kk < 32; kk++) {
            float4 bv = *(const float4*)&Ws[kk][lane * 4];
            float4 ga = *(const float4*)&Gst[kk][w * 8];        // broadcast
            float4 gb = *(const float4*)&Gst[kk][w * 8 + 4];    // broadcast
            float2 b01 = make_float2(bv.x, bv.y);
            float2 b23 = make_float2(bv.z, bv.w);
            float gs[8] = {ga.x, ga.y, ga.z, ga.w, gb.x, gb.y, gb.z, gb.w};
            #pragma unroll
            for (int i = 0; i < 8; i++) {
                float2 a2 = make_float2(gs[i], gs[i]);
                acc[i][0] = ffma2(a2, b01, acc[i][0]);
                acc[i][1] = ffma2(a2, b23, acc[i][1]);
            }
        }
        __syncthreads();
    }

    float* Pj = g_P + (size_t)j * (BATCH * DIM);
    #pragma unroll
    for (int i = 0; i < 8; i++) {
        int r = row0 + w * 8 + i;
        float4 v;
        v.x = acc[i][0].x; v.y = acc[i][0].y; v.z = acc[i][1].x; v.w = acc[i][1].y;
        *(float4*)(Pj + (size_t)r * DIM + lane * 4) = v;
    }
}

// ============================================================
// Kernel 3: out = elu(P0 + P1 + P2); 2 float4 per thread (MLP 6)
// ============================================================
__global__ __launch_bounds__(256) void epilogue_kernel(float* __restrict__ out) {
    int i0 = (blockIdx.x * 512 + threadIdx.x) * 4;
    int i1 = i0 + 1024;
    float4 a0 = *(const float4*)(g_P + i0);
    float4 b0 = *(const float4*)(g_P + BATCH * DIM + i0);
    float4 c0 = *(const float4*)(g_P + 2 * BATCH * DIM + i0);
    float4 a1 = *(const float4*)(g_P + i1);
    float4 b1 = *(const float4*)(g_P + BATCH * DIM + i1);
    float4 c1 = *(const float4*)(g_P + 2 * BATCH * DIM + i1);
    float4 v0, v1;
    v0.x = a0.x + b0.x + c0.x;  v0.y = a0.y + b0.y + c0.y;
    v0.z = a0.z + b0.z + c0.z;  v0.w = a0.w + b0.w + c0.w;
    v1.x = a1.x + b1.x + c1.x;  v1.y = a1.y + b1.y + c1.y;
    v1.z = a1.z + b1.z + c1.z;  v1.w = a1.w + b1.w + c1.w;
    v0.x = (v0.x > 0.f) ? v0.x : expm1f(v0.x);
    v0.y = (v0.y > 0.f) ? v0.y : expm1f(v0.y);
    v0.z = (v0.z > 0.f) ? v0.z : expm1f(v0.z);
    v0.w = (v0.w > 0.f) ? v0.w : expm1f(v0.w);
    v1.x = (v1.x > 0.f) ? v1.x : expm1f(v1.x);
    v1.y = (v1.y > 0.f) ? v1.y : expm1f(v1.y);
    v1.z = (v1.z > 0.f) ? v1.z : expm1f(v1.z);
    v1.w = (v1.w > 0.f) ? v1.w : expm1f(v1.w);
    *(float4*)(out + i0) = v0;
    *(float4*)(out + i1) = v1;
}

// ============================================================
extern "C" void kernel_launch(void* const* d_in, const int* in_sizes, int n_in,
                              void* d_out, int out_size) {
    const float* h    = (const float*)d_in[0];
    const void*  mask = d_in[1];
    const float* W    = (const float*)d_in[5];
    const float* a    = (const float*)d_in[6];
    float* out = (float*)d_out;

    prep_detect_kernel<<<13, 256>>>((const unsigned int*)mask, W, a);
    attn_kernel<<<BATCH, 128>>>(h, mask);
    gemm_split_kernel<<<dim3(128, 3), 256>>>(W);
    epilogue_kernel<<<(BATCH * DIM) / 2048, 256>>>(out);
}